// round 1
// baseline (speedup 1.0000x reference)
#include <cuda_runtime.h>
#include <cstdint>
#include <cstddef>

#define HH 192
#define WW 192
#define NPIX (HH * WW)      // 36864
#define CIN 128
#define NHEAD 8

// Scratch: rows 0-255 = q, 256-511 = k, 512-767 = v, each [256][NPIX]
__device__ float g_qkv[768 * NPIX];
// Per-head q.k dot at each pixel, pre-scaled by 1/TEMPER (1/16)
__device__ float g_s0[NHEAD * NPIX];

#define FMA2(d, a, b) asm("fma.rn.f32x2 %0, %1, %2, %0;" : "+l"(d) : "l"(a), "l"(b))
#define PACK2(out, x) asm("mov.b64 %0, {%1, %1};" : "=l"(out) : "r"(x))

__device__ __forceinline__ void cp16(uint32_t saddr, const void* g) {
    asm volatile("cp.async.cg.shared.global [%0], [%1], 16;\n" :: "r"(saddr), "l"(g));
}

// ---------------------------------------------------------------------------
// Kernel A: qkv = [wq;wk;wv] @ x   (M=768, N=36864, K=128), fp32 via FFMA2
// Block tile: BM=64, BN=128, BK=16; 256 threads; TM=4, TN=8 (split 4+4)
// ---------------------------------------------------------------------------
__global__ void __launch_bounds__(256, 3) qkv_gemm_kernel(
    const float* __restrict__ wq, const float* __restrict__ wk,
    const float* __restrict__ wv, const float* __restrict__ x)
{
    const int ASTR = 20;                 // padded k-stride (16B-aligned, bank-safe)
    __shared__ float As[2][64 * 20];     // [m][k]
    __shared__ float Bs[2][16 * 128];    // [k][n]

    const int t  = threadIdx.x;
    const int my = blockIdx.y;           // 0..11  (0-3 q, 4-7 k, 8-11 v)
    const int nx = blockIdx.x;           // 0..287

    const float* Aptr = (my < 4) ? (wq + my * 64 * CIN)
                      : (my < 8) ? (wk + (my - 4) * 64 * CIN)
                                 : (wv + (my - 8) * 64 * CIN);

    // A tile copy: thread t copies 16B at row am, k-offset ak4
    const int am  = t >> 2;
    const int ak4 = (t & 3) << 2;
    const float* Asrc = Aptr + am * CIN + ak4;

    // B tile copy: 2 chunks of 16B per thread (rows br, br+8)
    const int br = t >> 5;               // 0..7
    const int bc = (t & 31) << 2;        // 0..124
    const float* Bsrc = x + nx * 128 + bc;

    uint32_t sA[2], sB0[2], sB1[2];
#pragma unroll
    for (int b = 0; b < 2; b++) {
        sA[b]  = (uint32_t)__cvta_generic_to_shared(&As[b][am * ASTR + ak4]);
        sB0[b] = (uint32_t)__cvta_generic_to_shared(&Bs[b][br * 128 + bc]);
        sB1[b] = (uint32_t)__cvta_generic_to_shared(&Bs[b][(br + 8) * 128 + bc]);
    }

    auto issue_copy = [&](int kt) {
        const int buf = kt & 1;
        cp16(sA[buf],  Asrc + kt * 16);
        cp16(sB0[buf], Bsrc + (kt * 16 + br) * NPIX);
        cp16(sB1[buf], Bsrc + (kt * 16 + br + 8) * NPIX);
        asm volatile("cp.async.commit_group;\n");
    };

    issue_copy(0);
    issue_copy(1);

    const int tx = t & 15, ty = t >> 4;
    unsigned long long acc[4][4];
#pragma unroll
    for (int i = 0; i < 4; i++)
#pragma unroll
        for (int j = 0; j < 4; j++) acc[i][j] = 0ull;

    for (int kt = 0; kt < 8; kt++) {
        if (kt < 7) asm volatile("cp.async.wait_group 1;\n");
        else        asm volatile("cp.async.wait_group 0;\n");
        __syncthreads();
        const int buf = kt & 1;
        const float* Ab = &As[buf][ty * 4 * ASTR];
        const float* Bb = &Bs[buf][tx * 4];
#pragma unroll
        for (int k = 0; k < 16; k++) {
            const ulonglong2 b0 = *(const ulonglong2*)(Bb + k * 128);
            const ulonglong2 b1 = *(const ulonglong2*)(Bb + k * 128 + 64);
#pragma unroll
            for (int i = 0; i < 4; i++) {
                unsigned ar32 = __float_as_uint(Ab[i * ASTR + k]);
                unsigned long long ar;
                PACK2(ar, ar32);
                FMA2(acc[i][0], ar, b0.x);
                FMA2(acc[i][1], ar, b0.y);
                FMA2(acc[i][2], ar, b1.x);
                FMA2(acc[i][3], ar, b1.y);
            }
        }
        __syncthreads();
        if (kt + 2 < 8) issue_copy(kt + 2);
    }

    const int m0 = my * 64 + ty * 4;
    const int n0 = nx * 128 + tx * 4;
#pragma unroll
    for (int i = 0; i < 4; i++) {
        const float2* ap = (const float2*)acc[i];
        float4 r0 = make_float4(ap[0].x, ap[0].y, ap[1].x, ap[1].y);
        float4 r1 = make_float4(ap[2].x, ap[2].y, ap[3].x, ap[3].y);
        *(float4*)(&g_qkv[(m0 + i) * NPIX + n0])      = r0;
        *(float4*)(&g_qkv[(m0 + i) * NPIX + n0 + 64]) = r1;
    }
}

// ---------------------------------------------------------------------------
// Kernel B: s0[head][p] = (1/16) * sum_{c<32} q[head*32+c][p] * k[head*32+c][p]
// ---------------------------------------------------------------------------
__global__ void __launch_bounds__(256) s0_kernel()
{
    const int head = blockIdx.y;
    const int p = blockIdx.x * 256 + threadIdx.x;
    const float* q = g_qkv + (head * 32) * NPIX + p;
    const float* k = g_qkv + (256 + head * 32) * NPIX + p;
    float acc = 0.f;
#pragma unroll
    for (int c = 0; c < 32; c++)
        acc = fmaf(__ldg(q + c * NPIX), __ldg(k + c * NPIX), acc);
    g_s0[head * NPIX + p] = acc * 0.0625f;   // /TEMPER (=16)
}

// ---------------------------------------------------------------------------
// Kernel C: per-pixel softmax over 9 shifted s0 values (OOB slot -> logit 0,
// still inside the softmax), then out[c,p] = sum_s score * v[c, p+off_s].
// Block: 32 pixels (one row segment) x 256 channels; warp = one head.
// ---------------------------------------------------------------------------
__global__ void __launch_bounds__(256) attn_kernel(float* __restrict__ out)
{
    __shared__ float wsm[NHEAD * 9 * 32];   // [head][slot][pix]
    const int t  = threadIdx.x;
    const int h  = blockIdx.y;
    const int w0 = blockIdx.x * 32;

    // Phase 1: 32 pixels x 8 heads = 256 softmax tasks
    {
        const int pix = t & 31, head = t >> 5;
        const int w = w0 + pix;
        float lg[9];
#pragma unroll
        for (int s = 0; s < 9; s++) {
            const int hh = h + s / 3 - 1;
            const int ww = w + s % 3 - 1;
            const bool ok = ((unsigned)hh < HH) && ((unsigned)ww < WW);
            lg[s] = ok ? g_s0[head * NPIX + hh * WW + ww] : 0.0f;
        }
        float mx = lg[0];
#pragma unroll
        for (int s = 1; s < 9; s++) mx = fmaxf(mx, lg[s]);
        float e[9], sum = 0.f;
#pragma unroll
        for (int s = 0; s < 9; s++) { e[s] = __expf(lg[s] - mx); sum += e[s]; }
        const float inv = 1.0f / sum;
#pragma unroll
        for (int s = 0; s < 9; s++)
            wsm[(head * 9 + s) * 32 + pix] = e[s] * inv;
    }
    __syncthreads();

    // Phase 2: lane = pixel, warp = head; each warp does its 32 v-channels
    const int lane = t & 31, head = t >> 5;
    const int w = w0 + lane;
    float wr[9];
    int   off[9];
#pragma unroll
    for (int s = 0; s < 9; s++) {
        const int hh = h + s / 3 - 1;
        const int ww = w + s % 3 - 1;
        const bool ok = ((unsigned)hh < HH) && ((unsigned)ww < WW);
        const int hc = min(max(hh, 0), HH - 1);   // clamp: stays in-buffer,
        const int wc = min(max(ww, 0), WW - 1);   // weight 0 kills OOB value
        off[s] = hc * WW + wc;
        wr[s] = ok ? wsm[(head * 9 + s) * 32 + lane] : 0.0f;
    }
    const float* vbase = g_qkv + (512 + head * 32) * NPIX;
    float* obase = out + (head * 32) * NPIX + h * WW + w;
#pragma unroll 4
    for (int j = 0; j < 32; j++) {
        const float* vp = vbase + j * NPIX;
        float acc = 0.f;
#pragma unroll
        for (int s = 0; s < 9; s++)
            acc = fmaf(wr[s], __ldg(vp + off[s]), acc);
        obase[j * NPIX] = acc;
    }
}

// ---------------------------------------------------------------------------
extern "C" void kernel_launch(void* const* d_in, const int* in_sizes, int n_in,
                              void* d_out, int out_size)
{
    const float* x  = (const float*)d_in[0];
    const float* wq = (const float*)d_in[1];
    const float* wk = (const float*)d_in[2];
    const float* wv = (const float*)d_in[3];
    float* out = (float*)d_out;

    qkv_gemm_kernel<<<dim3(288, 12), 256>>>(wq, wk, wv, x);
    s0_kernel<<<dim3(NPIX / 256, NHEAD), 256>>>();
    attn_kernel<<<dim3(WW / 32, HH), 256>>>(out);
}

// round 4
// speedup vs baseline: 1.3652x; 1.3652x over previous
#include <cuda_runtime.h>
#include <cuda_bf16.h>
#include <cstdint>

#define HH 192
#define WW 192
#define NPIX (HH * WW)      // 36864
#define CIN 128
#define NHEAD 8
#define KSP 384             // split-K: [hi | lo | hi] for W, [hi | hi | lo] for x

// Scratch
__device__ float g_qkv[768 * NPIX];          // rows 0-255 q, 256-511 k, 512-767 v
__device__ float g_s0[NHEAD * NPIX];
__device__ __nv_bfloat16 g_wbf[768 * KSP];   // split weights, row-major [m][k]
__device__ __nv_bfloat16 g_xt[NPIX * KSP];   // split inputs, pixel-major [p][k]

// ---------------------------------------------------------------------------
// Helpers (base compute_103 features only: cp.async, ldmatrix, mma.sync)
// ---------------------------------------------------------------------------
__device__ __forceinline__ uint32_t smem_u32(const void* p) {
    uint32_t a;
    asm("{ .reg .u64 t; cvta.to.shared.u64 t, %1; cvt.u32.u64 %0, t; }" : "=r"(a) : "l"(p));
    return a;
}
__device__ __forceinline__ void cp16(uint32_t saddr, const void* g) {
    asm volatile("cp.async.cg.shared.global [%0], [%1], 16;\n" :: "r"(saddr), "l"(g));
}
__device__ __forceinline__ void ldsm_x4(uint32_t* r, uint32_t addr) {
    asm volatile("ldmatrix.sync.aligned.m8n8.x4.shared.b16 {%0,%1,%2,%3}, [%4];"
                 : "=r"(r[0]), "=r"(r[1]), "=r"(r[2]), "=r"(r[3]) : "r"(addr));
}
__device__ __forceinline__ void mma16816(float* d, const uint32_t* a, const uint32_t* b) {
    asm volatile(
        "mma.sync.aligned.m16n8k16.row.col.f32.bf16.bf16.f32 "
        "{%0,%1,%2,%3}, {%4,%5,%6,%7}, {%8,%9}, {%0,%1,%2,%3};"
        : "+f"(d[0]), "+f"(d[1]), "+f"(d[2]), "+f"(d[3])
        : "r"(a[0]), "r"(a[1]), "r"(a[2]), "r"(a[3]), "r"(b[0]), "r"(b[1]));
}

// ---------------------------------------------------------------------------
// Precompute 1: split weights -> g_wbf [768][384] = [hi | lo | hi]
// ---------------------------------------------------------------------------
__global__ void __launch_bounds__(128) wbf_kernel(
    const float* __restrict__ wq, const float* __restrict__ wk,
    const float* __restrict__ wv)
{
    const int m = blockIdx.x, c = threadIdx.x;
    const float* src = (m < 256) ? wq + m * CIN
                     : (m < 512) ? wk + (m - 256) * CIN
                                 : wv + (m - 512) * CIN;
    const float a = src[c];
    const __nv_bfloat16 hi = __float2bfloat16(a);
    const __nv_bfloat16 lo = __float2bfloat16(a - __bfloat162float(hi));
    g_wbf[m * KSP + c]       = hi;
    g_wbf[m * KSP + 128 + c] = lo;
    g_wbf[m * KSP + 256 + c] = hi;
}

// ---------------------------------------------------------------------------
// Precompute 2: transpose + split x -> g_xt [36864][384] = [hi | hi | lo]
// ---------------------------------------------------------------------------
__global__ void __launch_bounds__(256) xt_kernel(const float* __restrict__ x)
{
    __shared__ float tile[32][33];
    const int tx = threadIdx.x & 31, ty = threadIdx.x >> 5;  // ty 0..7
    const int p0 = blockIdx.x * 32, c0 = blockIdx.y * 32;
#pragma unroll
    for (int d = 0; d < 4; d++)
        tile[ty * 4 + d][tx] = x[(c0 + ty * 4 + d) * NPIX + p0 + tx];
    __syncthreads();
#pragma unroll
    for (int d = 0; d < 4; d++) {
        const int p = p0 + ty * 4 + d;
        const float a = tile[tx][ty * 4 + d];
        const __nv_bfloat16 hi = __float2bfloat16(a);
        const __nv_bfloat16 lo = __float2bfloat16(a - __bfloat162float(hi));
        g_xt[(size_t)p * KSP + c0 + tx]       = hi;
        g_xt[(size_t)p * KSP + 128 + c0 + tx] = hi;
        g_xt[(size_t)p * KSP + 256 + c0 + tx] = lo;
    }
}

// ---------------------------------------------------------------------------
// Kernel A: qkv = W' @ X'^T via mma.sync bf16 (HMMA). CTA 128x128, BK=32,
// 3-stage cp.async pipeline, 8 warps (2m x 4n), warp tile 64x32.
// SMEM rows padded to 80B (stride 5 in 16B units -> ldmatrix conflict-free).
// ---------------------------------------------------------------------------
#define ASTRB 80                      // bytes per padded SMEM row (64 data + 16 pad)
#define STG_BYTES (128 * ASTRB)       // 10240 per operand per stage
#define SMEM_GEMM (6 * STG_BYTES)     // 3 stages x (A + B) = 61440 B

__global__ void __launch_bounds__(256, 2) qkv_mma_kernel()
{
    extern __shared__ __align__(128) char smem[];
    const uint32_t sbase = smem_u32(smem);
    const int t = threadIdx.x, lane = t & 31, w = t >> 5;
    const int wm = w >> 2, wn = w & 3;
    const int m0 = blockIdx.y * 128;
    const int n0 = blockIdx.x * 128;

    const __nv_bfloat16* Ag = g_wbf + (size_t)m0 * KSP;
    const __nv_bfloat16* Bg = g_xt  + (size_t)n0 * KSP;

    // Per-thread copy mapping: chunks t and t+256 of 512 16B-chunks per operand
    const int r0c = t >> 2, c0c = t & 3;          // chunk t
    const int r1c = (t + 256) >> 2, c1c = t & 3;  // chunk t+256 (same col bits)

    auto issue_copy = [&](int kt) {
        const int s = kt % 3;
        const uint32_t sA = sbase + s * STG_BYTES;
        const uint32_t sB = sbase + 3 * STG_BYTES + s * STG_BYTES;
        cp16(sA + r0c * ASTRB + c0c * 16, Ag + (size_t)r0c * KSP + kt * 32 + c0c * 8);
        cp16(sB + r0c * ASTRB + c0c * 16, Bg + (size_t)r0c * KSP + kt * 32 + c0c * 8);
        cp16(sA + r1c * ASTRB + c1c * 16, Ag + (size_t)r1c * KSP + kt * 32 + c1c * 8);
        cp16(sB + r1c * ASTRB + c1c * 16, Bg + (size_t)r1c * KSP + kt * 32 + c1c * 8);
        asm volatile("cp.async.commit_group;\n");
    };

    issue_copy(0);
    issue_copy(1);

    float acc[4][4][4];
#pragma unroll
    for (int i = 0; i < 4; i++)
#pragma unroll
        for (int j = 0; j < 4; j++)
#pragma unroll
            for (int e = 0; e < 4; e++) acc[i][j][e] = 0.f;

    // Precomputed per-lane ldmatrix offsets (within a stage)
    const uint32_t aRow = (uint32_t)(wm * 64 + (lane & 15));
    const uint32_t aChunkLane = (uint32_t)(lane >> 4);      // 0/1
    const int bsel = lane >> 3, br = lane & 7;
    const uint32_t bRowBase = (uint32_t)(wn * 32 + ((bsel >> 1) << 3) + br);
    const uint32_t bChunkLane = (uint32_t)(bsel & 1);

#pragma unroll 1
    for (int kt = 0; kt < 12; kt++) {
        if (kt < 11) asm volatile("cp.async.wait_group 1;\n" ::: "memory");
        else         asm volatile("cp.async.wait_group 0;\n" ::: "memory");
        __syncthreads();
        if (kt + 2 < 12) issue_copy(kt + 2);

        const int s = kt % 3;
        const uint32_t sA = sbase + s * STG_BYTES;
        const uint32_t sB = sbase + 3 * STG_BYTES + s * STG_BYTES;

#pragma unroll
        for (int ks = 0; ks < 2; ks++) {
            uint32_t afr[4][4];
#pragma unroll
            for (int mi = 0; mi < 4; mi++)
                ldsm_x4(afr[mi], sA + (aRow + mi * 16) * ASTRB
                                    + (ks * 2 + aChunkLane) * 16);
            uint32_t bfr[4][2];
#pragma unroll
            for (int ni2 = 0; ni2 < 2; ni2++) {
                uint32_t rr[4];
                ldsm_x4(rr, sB + (bRowBase + ni2 * 16) * ASTRB
                               + (ks * 2 + bChunkLane) * 16);
                bfr[ni2 * 2 + 0][0] = rr[0]; bfr[ni2 * 2 + 0][1] = rr[1];
                bfr[ni2 * 2 + 1][0] = rr[2]; bfr[ni2 * 2 + 1][1] = rr[3];
            }
#pragma unroll
            for (int mi = 0; mi < 4; mi++)
#pragma unroll
                for (int nj = 0; nj < 4; nj++)
                    mma16816(acc[mi][nj], afr[mi], bfr[nj]);
        }
        __syncthreads();
    }

    // Epilogue: direct float2 stores (quad-coalesced 32B sectors)
    const int mBase = m0 + wm * 64 + (lane >> 2);
    const int pBase = n0 + wn * 32 + (lane & 3) * 2;
#pragma unroll
    for (int mi = 0; mi < 4; mi++) {
#pragma unroll
        for (int nj = 0; nj < 4; nj++) {
            const size_t i0 = (size_t)(mBase + mi * 16) * NPIX + pBase + nj * 8;
            const size_t i1 = i0 + 8 * NPIX;
            *(float2*)&g_qkv[i0] = make_float2(acc[mi][nj][0], acc[mi][nj][1]);
            *(float2*)&g_qkv[i1] = make_float2(acc[mi][nj][2], acc[mi][nj][3]);
        }
    }
}

// ---------------------------------------------------------------------------
// Kernel B: s0[head][p] = (1/16) * sum_{c<32} q[c][p] * k[c][p]
// ---------------------------------------------------------------------------
__global__ void __launch_bounds__(256) s0_kernel()
{
    const int head = blockIdx.y;
    const int p = blockIdx.x * 256 + threadIdx.x;
    const float* q = g_qkv + (head * 32) * NPIX + p;
    const float* k = g_qkv + (256 + head * 32) * NPIX + p;
    float acc = 0.f;
#pragma unroll
    for (int c = 0; c < 32; c++)
        acc = fmaf(__ldg(q + c * NPIX), __ldg(k + c * NPIX), acc);
    g_s0[head * NPIX + p] = acc * 0.0625f;
}

// ---------------------------------------------------------------------------
// Kernel C: per-pixel softmax over 9 shifted s0 (OOB -> logit 0), then
// out[c,p] = sum_s score * v[c, p+off_s].
// ---------------------------------------------------------------------------
__global__ void __launch_bounds__(256) attn_kernel(float* __restrict__ out)
{
    __shared__ float wsm[NHEAD * 9 * 32];
    const int t = threadIdx.x;
    const int h = blockIdx.y;
    const int w0 = blockIdx.x * 32;

    {
        const int pix = t & 31, head = t >> 5;
        const int w = w0 + pix;
        float lg[9];
#pragma unroll
        for (int s = 0; s < 9; s++) {
            const int hh = h + s / 3 - 1;
            const int ww = w + s % 3 - 1;
            const bool ok = ((unsigned)hh < HH) && ((unsigned)ww < WW);
            lg[s] = ok ? g_s0[head * NPIX + hh * WW + ww] : 0.0f;
        }
        float mx = lg[0];
#pragma unroll
        for (int s = 1; s < 9; s++) mx = fmaxf(mx, lg[s]);
        float e[9], sum = 0.f;
#pragma unroll
        for (int s = 0; s < 9; s++) { e[s] = __expf(lg[s] - mx); sum += e[s]; }
        const float inv = 1.0f / sum;
#pragma unroll
        for (int s = 0; s < 9; s++)
            wsm[(head * 9 + s) * 32 + pix] = e[s] * inv;
    }
    __syncthreads();

    const int lane = t & 31, head = t >> 5;
    const int w = w0 + lane;
    float wr[9];
    int off[9];
#pragma unroll
    for (int s = 0; s < 9; s++) {
        const int hh = h + s / 3 - 1;
        const int ww = w + s % 3 - 1;
        const bool ok = ((unsigned)hh < HH) && ((unsigned)ww < WW);
        const int hc = min(max(hh, 0), HH - 1);
        const int wc = min(max(ww, 0), WW - 1);
        off[s] = hc * WW + wc;
        wr[s] = ok ? wsm[(head * 9 + s) * 32 + lane] : 0.0f;
    }
    const float* vbase = g_qkv + (512 + head * 32) * NPIX;
    float* obase = out + (head * 32) * NPIX + h * WW + w;
#pragma unroll 4
    for (int j = 0; j < 32; j++) {
        const float* vp = vbase + j * NPIX;
        float acc = 0.f;
#pragma unroll
        for (int s = 0; s < 9; s++)
            acc = fmaf(wr[s], __ldg(vp + off[s]), acc);
        obase[j * NPIX] = acc;
    }
}

// ---------------------------------------------------------------------------
extern "C" void kernel_launch(void* const* d_in, const int* in_sizes, int n_in,
                              void* d_out, int out_size)
{
    const float* x  = (const float*)d_in[0];
    const float* wq = (const float*)d_in[1];
    const float* wk = (const float*)d_in[2];
    const float* wv = (const float*)d_in[3];
    float* out = (float*)d_out;

    cudaFuncSetAttribute(qkv_mma_kernel,
                         cudaFuncAttributeMaxDynamicSharedMemorySize, SMEM_GEMM);

    wbf_kernel<<<768, 128>>>(wq, wk, wv);
    xt_kernel<<<dim3(NPIX / 32, 4), 256>>>(x);
    qkv_mma_kernel<<<dim3(288, 6), 256, SMEM_GEMM>>>();
    s0_kernel<<<dim3(NPIX / 256, NHEAD), 256>>>();
    attn_kernel<<<dim3(WW / 32, HH), 256>>>(out);
}

// round 6
// speedup vs baseline: 1.7911x; 1.3119x over previous
#include <cuda_runtime.h>
#include <cuda_bf16.h>
#include <cstdint>

#define HH 192
#define WW 192
#define NPIX (HH * WW)      // 36864
#define CIN 128
#define NHEAD 8
#define KST 256             // [hi(128) | lo(128)] storage; 3 split terms via k remap

// Scratch
__device__ float g_v[256 * NPIX];            // v projection
__device__ float g_s0[NHEAD * NPIX];         // per-head q.k / 16
__device__ __nv_bfloat16 g_wbf[768 * KST];   // rows 0-511: [q_h|k_h] interleaved per head (64 rows/head); 512-767: v
__device__ __nv_bfloat16 g_xt[NPIX * KST];   // x transposed, [p][hi|lo]

// ---------------------------------------------------------------------------
// Helpers (base compute_103 features only: cp.async, ldmatrix, mma.sync)
// ---------------------------------------------------------------------------
__device__ __forceinline__ uint32_t smem_u32(const void* p) {
    uint32_t a;
    asm("{ .reg .u64 t; cvta.to.shared.u64 t, %1; cvt.u32.u64 %0, t; }" : "=r"(a) : "l"(p));
    return a;
}
__device__ __forceinline__ void cp16(uint32_t saddr, const void* g) {
    asm volatile("cp.async.cg.shared.global [%0], [%1], 16;\n" :: "r"(saddr), "l"(g));
}
__device__ __forceinline__ void ldsm_x4(uint32_t* r, uint32_t addr) {
    asm volatile("ldmatrix.sync.aligned.m8n8.x4.shared.b16 {%0,%1,%2,%3}, [%4];"
                 : "=r"(r[0]), "=r"(r[1]), "=r"(r[2]), "=r"(r[3]) : "r"(addr));
}
__device__ __forceinline__ void mma16816(float* d, const uint32_t* a, const uint32_t* b) {
    asm volatile(
        "mma.sync.aligned.m16n8k16.row.col.f32.bf16.bf16.f32 "
        "{%0,%1,%2,%3}, {%4,%5,%6,%7}, {%8,%9}, {%0,%1,%2,%3};"
        : "+f"(d[0]), "+f"(d[1]), "+f"(d[2]), "+f"(d[3])
        : "r"(a[0]), "r"(a[1]), "r"(a[2]), "r"(a[3]), "r"(b[0]), "r"(b[1]));
}

// Split-term k offsets (bf16 elements) per 32-wide K chunk kt in [0,12):
//   term 0 (kt 0-3):  A=hi, B=hi     term 1 (kt 4-7): A=lo, B=hi
//   term 2 (kt 8-11): A=hi, B=lo
__device__ __forceinline__ int kOffA(int kt) {
    return (kt < 4) ? kt * 32 : (kt < 8) ? 128 + (kt - 4) * 32 : (kt - 8) * 32;
}
__device__ __forceinline__ int kOffB(int kt) {
    return (kt < 4) ? kt * 32 : (kt < 8) ? (kt - 4) * 32 : 128 + (kt - 8) * 32;
}

// ---------------------------------------------------------------------------
// Precompute 1: split weights -> g_wbf [768][256] = [hi | lo]
// Row order: r < 512: head h = r/64, j = r%64; j<32 -> q-row, else k-row.
//            r >= 512: v row (r-512).
// ---------------------------------------------------------------------------
__global__ void __launch_bounds__(128) wbf_kernel(
    const float* __restrict__ wq, const float* __restrict__ wk,
    const float* __restrict__ wv)
{
    const int r = blockIdx.x, c = threadIdx.x;
    const float* src;
    if (r < 512) {
        const int h = r >> 6, j = r & 63;
        src = (j < 32) ? wq + (h * 32 + j) * CIN
                       : wk + (h * 32 + j - 32) * CIN;
    } else {
        src = wv + (r - 512) * CIN;
    }
    const float a = src[c];
    const __nv_bfloat16 hi = __float2bfloat16(a);
    const __nv_bfloat16 lo = __float2bfloat16(a - __bfloat162float(hi));
    g_wbf[r * KST + c]       = hi;
    g_wbf[r * KST + 128 + c] = lo;
}

// ---------------------------------------------------------------------------
// Precompute 2: transpose + split x -> g_xt [36864][256] = [hi | lo]
// ---------------------------------------------------------------------------
__global__ void __launch_bounds__(256) xt_kernel(const float* __restrict__ x)
{
    __shared__ float tile[32][33];
    const int tx = threadIdx.x & 31, ty = threadIdx.x >> 5;
    const int p0 = blockIdx.x * 32, c0 = blockIdx.y * 32;
#pragma unroll
    for (int d = 0; d < 4; d++)
        tile[ty * 4 + d][tx] = x[(c0 + ty * 4 + d) * NPIX + p0 + tx];
    __syncthreads();
#pragma unroll
    for (int d = 0; d < 4; d++) {
        const int p = p0 + ty * 4 + d;
        const float a = tile[tx][ty * 4 + d];
        const __nv_bfloat16 hi = __float2bfloat16(a);
        const __nv_bfloat16 lo = __float2bfloat16(a - __bfloat162float(hi));
        g_xt[(size_t)p * KST + c0 + tx]       = hi;
        g_xt[(size_t)p * KST + 128 + c0 + tx] = lo;
    }
}

// ---------------------------------------------------------------------------
// Kernel A: HMMA GEMM, CTA 128x128, BK=32, 3-stage cp.async, 8 warps (2m x 4n).
// blockIdx.y 0-3: q/k tiles -> fused s0 epilogue (no q,k gmem writes).
// blockIdx.y 4-5: v tiles   -> standard epilogue into g_v.
// ---------------------------------------------------------------------------
#define ASTRB 80                      // padded SMEM row bytes (64 data + 16)
#define STG_BYTES (128 * ASTRB)
#define SMEM_GEMM (6 * STG_BYTES)     // 61440 B

__global__ void __launch_bounds__(256, 2) qkv_mma_kernel()
{
    extern __shared__ __align__(128) char smem[];
    const uint32_t sbase = smem_u32(smem);
    const int t = threadIdx.x, lane = t & 31, w = t >> 5;
    const int wm = w >> 2, wn = w & 3;
    const int by = blockIdx.y;
    const int m0 = by * 128;
    const int n0 = blockIdx.x * 128;

    const __nv_bfloat16* Ag = g_wbf + (size_t)m0 * KST;
    const __nv_bfloat16* Bg = g_xt  + (size_t)n0 * KST;

    const int r0c = t >> 2, c0c = t & 3;
    const int r1c = r0c + 64;

    auto issue_copy = [&](int kt) {
        const int s = kt % 3;
        const int ka = kOffA(kt), kb = kOffB(kt);
        const uint32_t sA = sbase + s * STG_BYTES;
        const uint32_t sB = sbase + 3 * STG_BYTES + s * STG_BYTES;
        cp16(sA + r0c * ASTRB + c0c * 16, Ag + (size_t)r0c * KST + ka + c0c * 8);
        cp16(sB + r0c * ASTRB + c0c * 16, Bg + (size_t)r0c * KST + kb + c0c * 8);
        cp16(sA + r1c * ASTRB + c0c * 16, Ag + (size_t)r1c * KST + ka + c0c * 8);
        cp16(sB + r1c * ASTRB + c0c * 16, Bg + (size_t)r1c * KST + kb + c0c * 8);
        asm volatile("cp.async.commit_group;\n");
    };

    issue_copy(0);
    issue_copy(1);

    float acc[4][4][4];
#pragma unroll
    for (int i = 0; i < 4; i++)
#pragma unroll
        for (int j = 0; j < 4; j++)
#pragma unroll
            for (int e = 0; e < 4; e++) acc[i][j][e] = 0.f;

    const uint32_t aRow = (uint32_t)(wm * 64 + (lane & 15));
    const uint32_t aChunkLane = (uint32_t)(lane >> 4);
    const int bsel = lane >> 3, br = lane & 7;
    const uint32_t bRowBase = (uint32_t)(wn * 32 + ((bsel >> 1) << 3) + br);
    const uint32_t bChunkLane = (uint32_t)(bsel & 1);

#pragma unroll 1
    for (int kt = 0; kt < 12; kt++) {
        if (kt < 11) asm volatile("cp.async.wait_group 1;\n" ::: "memory");
        else         asm volatile("cp.async.wait_group 0;\n" ::: "memory");
        __syncthreads();
        if (kt + 2 < 12) issue_copy(kt + 2);

        const int s = kt % 3;
        const uint32_t sA = sbase + s * STG_BYTES;
        const uint32_t sB = sbase + 3 * STG_BYTES + s * STG_BYTES;

#pragma unroll
        for (int ks = 0; ks < 2; ks++) {
            uint32_t afr[4][4];
#pragma unroll
            for (int mi = 0; mi < 4; mi++)
                ldsm_x4(afr[mi], sA + (aRow + mi * 16) * ASTRB
                                    + (ks * 2 + aChunkLane) * 16);
            uint32_t bfr[4][2];
#pragma unroll
            for (int ni2 = 0; ni2 < 2; ni2++) {
                uint32_t rr[4];
                ldsm_x4(rr, sB + (bRowBase + ni2 * 16) * ASTRB
                               + (ks * 2 + bChunkLane) * 16);
                bfr[ni2 * 2 + 0][0] = rr[0]; bfr[ni2 * 2 + 0][1] = rr[1];
                bfr[ni2 * 2 + 1][0] = rr[2]; bfr[ni2 * 2 + 1][1] = rr[3];
            }
#pragma unroll
            for (int mi = 0; mi < 4; mi++)
#pragma unroll
                for (int nj = 0; nj < 4; nj++)
                    mma16816(acc[mi][nj], afr[mi], bfr[nj]);
        }
        __syncthreads();
    }

    if (by < 4) {
        // Fused s0 epilogue. Warp tile = 64 rows = one head's q(32)+k(32).
        // q channel j lives at acc[mi][..] (mi 0,1), k channel j at acc[mi+2][..],
        // same lane & element. Reduce over mi/e-halves in-thread, over lane>>2
        // by butterfly shuffle.
        const int head = 2 * by + wm;
        float part[4][2];
#pragma unroll
        for (int nj = 0; nj < 4; nj++)
#pragma unroll
            for (int pe = 0; pe < 2; pe++)
                part[nj][pe] = acc[0][nj][pe]     * acc[2][nj][pe]
                             + acc[1][nj][pe]     * acc[3][nj][pe]
                             + acc[0][nj][pe + 2] * acc[2][nj][pe + 2]
                             + acc[1][nj][pe + 2] * acc[3][nj][pe + 2];
#pragma unroll
        for (int d = 4; d <= 16; d <<= 1)
#pragma unroll
            for (int nj = 0; nj < 4; nj++)
#pragma unroll
                for (int pe = 0; pe < 2; pe++)
                    part[nj][pe] += __shfl_xor_sync(0xffffffffu, part[nj][pe], d);
        if ((lane >> 2) == 0) {
            float* dst = g_s0 + (size_t)head * NPIX + n0 + wn * 32 + (lane & 3) * 2;
#pragma unroll
            for (int nj = 0; nj < 4; nj++) {
                dst[nj * 8]     = part[nj][0] * 0.0625f;
                dst[nj * 8 + 1] = part[nj][1] * 0.0625f;
            }
        }
    } else {
        // v epilogue: direct float2 stores
        const int mBase = (by - 4) * 128 + wm * 64 + (lane >> 2);
        const int pBase = n0 + wn * 32 + (lane & 3) * 2;
#pragma unroll
        for (int mi = 0; mi < 4; mi++) {
#pragma unroll
            for (int nj = 0; nj < 4; nj++) {
                const size_t i0 = (size_t)(mBase + mi * 16) * NPIX + pBase + nj * 8;
                const size_t i1 = i0 + 8 * NPIX;
                *(float2*)&g_v[i0] = make_float2(acc[mi][nj][0], acc[mi][nj][1]);
                *(float2*)&g_v[i1] = make_float2(acc[mi][nj][2], acc[mi][nj][3]);
            }
        }
    }
}

// ---------------------------------------------------------------------------
// Kernel C: per-pixel softmax over 9 shifted s0 (OOB -> logit 0), then
// out[c,p] = sum_s score * v[c, p+off_s].
// ---------------------------------------------------------------------------
__global__ void __launch_bounds__(256) attn_kernel(float* __restrict__ out)
{
    __shared__ float wsm[NHEAD * 9 * 32];
    const int t = threadIdx.x;
    const int h = blockIdx.y;
    const int w0 = blockIdx.x * 32;

    {
        const int pix = t & 31, head = t >> 5;
        const int w = w0 + pix;
        float lg[9];
#pragma unroll
        for (int s = 0; s < 9; s++) {
            const int hh = h + s / 3 - 1;
            const int ww = w + s % 3 - 1;
            const bool ok = ((unsigned)hh < HH) && ((unsigned)ww < WW);
            lg[s] = ok ? g_s0[head * NPIX + hh * WW + ww] : 0.0f;
        }
        float mx = lg[0];
#pragma unroll
        for (int s = 1; s < 9; s++) mx = fmaxf(mx, lg[s]);
        float e[9], sum = 0.f;
#pragma unroll
        for (int s = 0; s < 9; s++) { e[s] = __expf(lg[s] - mx); sum += e[s]; }
        const float inv = 1.0f / sum;
#pragma unroll
        for (int s = 0; s < 9; s++)
            wsm[(head * 9 + s) * 32 + pix] = e[s] * inv;
    }
    __syncthreads();

    const int lane = t & 31, head = t >> 5;
    const int w = w0 + lane;
    float wr[9];
    int off[9];
#pragma unroll
    for (int s = 0; s < 9; s++) {
        const int hh = h + s / 3 - 1;
        const int ww = w + s % 3 - 1;
        const bool ok = ((unsigned)hh < HH) && ((unsigned)ww < WW);
        const int hc = min(max(hh, 0), HH - 1);
        const int wc = min(max(ww, 0), WW - 1);
        off[s] = hc * WW + wc;
        wr[s] = ok ? wsm[(head * 9 + s) * 32 + lane] : 0.0f;
    }
    const float* vbase = g_v + (head * 32) * NPIX;
    float* obase = out + (head * 32) * NPIX + h * WW + w;
#pragma unroll 4
    for (int j = 0; j < 32; j++) {
        const float* vp = vbase + j * NPIX;
        float acc = 0.f;
#pragma unroll
        for (int s = 0; s < 9; s++)
            acc = fmaf(wr[s], __ldg(vp + off[s]), acc);
        obase[j * NPIX] = acc;
    }
}

// ---------------------------------------------------------------------------
extern "C" void kernel_launch(void* const* d_in, const int* in_sizes, int n_in,
                              void* d_out, int out_size)
{
    const float* x  = (const float*)d_in[0];
    const float* wq = (const float*)d_in[1];
    const float* wk = (const float*)d_in[2];
    const float* wv = (const float*)d_in[3];
    float* out = (float*)d_out;

    cudaFuncSetAttribute(qkv_mma_kernel,
                         cudaFuncAttributeMaxDynamicSharedMemorySize, SMEM_GEMM);

    wbf_kernel<<<768, 128>>>(wq, wk, wv);
    xt_kernel<<<dim3(NPIX / 32, 4), 256>>>(x);
    qkv_mma_kernel<<<dim3(288, 6), 256, SMEM_GEMM>>>();
    attn_kernel<<<dim3(WW / 32, HH), 256>>>(out);
}